// round 14
// baseline (speedup 1.0000x reference)
#include <cuda_runtime.h>
#include <cuda_fp16.h>
#include <math.h>
#include <stdint.h>

#define D_DIM 1536
#define E_NUM 64
#define H_DIM 384
#define TOPK  8
#define CAP   1024
#define T_NUM 4096

// ---------------- scratch (static device globals; no allocations) ----------
__device__ __align__(16) int      g_counts[E_NUM];
__device__ __align__(16) int      g_slot_token[E_NUM * CAP];
__device__ __align__(16) float    g_slot_weight[E_NUM * CAP];
__device__ __align__(16) int      g_tok_slot[T_NUM * TOPK];
__device__ __align__(16) __half   g_xh[(size_t)T_NUM * D_DIM];                // 12.6 MB
__device__ __align__(16) uint32_t g_wgf[(size_t)E_NUM * 96 * 48 * 32 * 2];    // 75 MB
__device__ __align__(16) uint32_t g_wuf[(size_t)E_NUM * 96 * 48 * 32 * 2];    // 75 MB
__device__ __align__(16) uint32_t g_wdf[(size_t)E_NUM * 24 * 192 * 32 * 2];   // 75 MB
__device__ __align__(16) uint32_t g_actf[(size_t)E_NUM * 64 * 24 * 128];      // 50 MB
__device__ __align__(16) __half   g_yh[(size_t)E_NUM * CAP * D_DIM];          // 201 MB

// ---------------- helpers ----------------------------------------------------
__device__ __forceinline__ uint32_t pack_h2(float lo, float hi) {
    __half2 h = __floats2half2_rn(lo, hi);
    return *(uint32_t*)&h;
}
__device__ __forceinline__ uint32_t smem_u32(const void* p) {
    return (uint32_t)__cvta_generic_to_shared(p);
}
__device__ __forceinline__ void cp16(uint32_t dst, const void* src) {
    asm volatile("cp.async.cg.shared.global [%0], [%1], 16;"
                 :: "r"(dst), "l"(src) : "memory");
}
__device__ __forceinline__ void cp_commit() {
    asm volatile("cp.async.commit_group;" ::: "memory");
}
template <int N>
__device__ __forceinline__ void cp_wait() {
    asm volatile("cp.async.wait_group %0;" :: "n"(N) : "memory");
}
__device__ __forceinline__ void ldmx4(uint32_t& a0, uint32_t& a1,
                                      uint32_t& a2, uint32_t& a3, uint32_t addr) {
    asm volatile("ldmatrix.sync.aligned.m8n8.x4.shared.b16 {%0,%1,%2,%3}, [%4];"
                 : "=r"(a0), "=r"(a1), "=r"(a2), "=r"(a3) : "r"(addr));
}
__device__ __forceinline__ void mma16816(float c[4],
                                         uint32_t a0, uint32_t a1, uint32_t a2, uint32_t a3,
                                         uint32_t b0, uint32_t b1) {
    asm volatile(
        "mma.sync.aligned.m16n8k16.row.col.f32.f16.f16.f32 "
        "{%0,%1,%2,%3}, {%4,%5,%6,%7}, {%8,%9}, {%0,%1,%2,%3};"
        : "+f"(c[0]), "+f"(c[1]), "+f"(c[2]), "+f"(c[3])
        : "r"(a0), "r"(a1), "r"(a2), "r"(a3), "r"(b0), "r"(b1));
}
__device__ __forceinline__ float silu(float g) { return g / (1.f + expf(-g)); }

// ---------------- kernel 0: init counters -----------------------------------
__global__ void init_kernel() {
    if (threadIdx.x < E_NUM) g_counts[threadIdx.x] = 0;
}

// =============================================================================
// fused prep kernel: router FIRST (overlaps with converters), then converters.
// Blocks [0,512): router; [512,6656): convert_gu; [6656,8192): convert_d.
// =============================================================================
#define NB_R  512
#define NB_GU 6144
#define NB_D  1536

extern __shared__ float s_dyn[];

__device__ __forceinline__ void convert_gu_body(
    int bid, const float* __restrict__ Wg, const float* __restrict__ Wu)
{
    const int kc = bid % 96, e = bid / 96;
    const int tid = threadIdx.x, lane = tid & 31, g = lane >> 2, t = lane & 3;
    const size_t wbase = (size_t)e * D_DIM * H_DIM + (size_t)(16 * kc + 2 * t) * H_DIM;
    const float* wg0 = Wg + wbase;
    const float* wu0 = Wu + wbase;
    uint2* og = (uint2*)g_wgf;
    uint2* ou = (uint2*)g_wuf;
#pragma unroll
    for (int p = 0; p < 6; p++) {
        const int nt = (tid >> 5) + 8 * p;
        const int n = 8 * nt + g;
        const size_t oi = ((size_t)(e * 96 + kc) * 48 + nt) * 32 + lane;
        og[oi] = make_uint2(pack_h2(wg0[n], wg0[H_DIM + n]),
                            pack_h2(wg0[8 * H_DIM + n], wg0[9 * H_DIM + n]));
        ou[oi] = make_uint2(pack_h2(wu0[n], wu0[H_DIM + n]),
                            pack_h2(wu0[8 * H_DIM + n], wu0[9 * H_DIM + n]));
    }
}

__device__ __forceinline__ void convert_d_body(
    int bid, const float* __restrict__ Wd)
{
    const int kc = bid % 24, e = bid / 24;
    const int tid = threadIdx.x, lane = tid & 31, g = lane >> 2, t = lane & 3;
    const float* wd0 = Wd + (size_t)e * H_DIM * D_DIM + (size_t)(16 * kc + 2 * t) * D_DIM;
    uint2* od = (uint2*)g_wdf;
#pragma unroll
    for (int p = 0; p < 24; p++) {
        const int nt = (tid >> 5) + 8 * p;
        const int n = 8 * nt + g;
        od[((size_t)(e * 24 + kc) * 192 + nt) * 32 + lane] =
            make_uint2(pack_h2(wd0[n], wd0[D_DIM + n]),
                       pack_h2(wd0[8 * D_DIM + n], wd0[9 * D_DIM + n]));
    }
}

__device__ __forceinline__ void router_body(
    int rbid, const float* __restrict__ x, const float* __restrict__ gate_w)
{
    float (*xs)[D_DIM] = (float (*)[D_DIM])s_dyn;
    float (*lg)[E_NUM] = (float (*)[E_NUM])(s_dyn + 8 * D_DIM);

    const int tid = threadIdx.x;
    const int t0 = rbid * 8;

    const float4* xg = (const float4*)(x + (size_t)t0 * D_DIM);
    float4* xs4 = (float4*)xs;
    for (int i = tid; i < 8 * D_DIM / 4; i += 256) xs4[i] = xg[i];
    __syncthreads();

    // fused convert_x: write fp16 copy of these 8 rows
    {
        uint2* xh2 = (uint2*)(g_xh + (size_t)t0 * D_DIM);
        const float4* xsc = (const float4*)xs;
        for (int i = tid; i < 8 * D_DIM / 4; i += 256) {
            float4 v = xsc[i];
            xh2[i] = make_uint2(pack_h2(v.x, v.y), pack_h2(v.z, v.w));
        }
    }

    const int warp = tid >> 5, lane = tid & 31;

    // logits: 8 experts x 8 tokens per warp, k-slice outer product
    {
        const int e0 = warp * 8;
        float acc[8][8];
#pragma unroll
        for (int j = 0; j < 8; j++)
#pragma unroll
            for (int t = 0; t < 8; t++) acc[j][t] = 0.f;

        for (int d4 = lane; d4 < D_DIM / 4; d4 += 32) {
            float4 xv[8];
#pragma unroll
            for (int t = 0; t < 8; t++)
                xv[t] = *(const float4*)(&xs[t][d4 * 4]);
            float4 gv[8];
#pragma unroll
            for (int j = 0; j < 8; j++)
                gv[j] = *(const float4*)(gate_w + (size_t)(e0 + j) * D_DIM + d4 * 4);
#pragma unroll
            for (int j = 0; j < 8; j++)
#pragma unroll
                for (int t = 0; t < 8; t++)
                    acc[j][t] = fmaf(gv[j].x, xv[t].x, fmaf(gv[j].y, xv[t].y,
                                 fmaf(gv[j].z, xv[t].z, fmaf(gv[j].w, xv[t].w,
                                 acc[j][t]))));
        }
#pragma unroll
        for (int off = 16; off > 0; off >>= 1)
#pragma unroll
            for (int j = 0; j < 8; j++)
#pragma unroll
                for (int t = 0; t < 8; t++)
                    acc[j][t] += __shfl_xor_sync(0xffffffffu, acc[j][t], off);
        if (lane == 0)
#pragma unroll
            for (int j = 0; j < 8; j++)
#pragma unroll
                for (int t = 0; t < 8; t++) lg[t][e0 + j] = acc[j][t];
    }
    __syncthreads();

    // softmax + top-8 + renorm + dispatch (warp w = token w)
    {
        const int t = warp;
        float v0 = lg[t][lane];
        float v1 = lg[t][lane + 32];
        float m = fmaxf(v0, v1);
#pragma unroll
        for (int off = 16; off > 0; off >>= 1)
            m = fmaxf(m, __shfl_xor_sync(0xffffffffu, m, off));
        float e0 = expf(v0 - m), e1 = expf(v1 - m);
        float s = e0 + e1;
#pragma unroll
        for (int off = 16; off > 0; off >>= 1)
            s += __shfl_xor_sync(0xffffffffu, s, off);
        float p0 = e0 / s, p1 = e1 / s;

        float selw[TOPK];
        int   sele[TOPK];
#pragma unroll
        for (int k = 0; k < TOPK; k++) {
            float bv; int bi;
            if (p0 >= p1) { bv = p0; bi = lane; }
            else          { bv = p1; bi = lane + 32; }
#pragma unroll
            for (int off = 16; off > 0; off >>= 1) {
                float ov = __shfl_xor_sync(0xffffffffu, bv, off);
                int   oi = __shfl_xor_sync(0xffffffffu, bi, off);
                if (ov > bv || (ov == bv && oi < bi)) { bv = ov; bi = oi; }
            }
            selw[k] = bv; sele[k] = bi;
            if (bi == lane)      p0 = -1.f;
            if (bi == lane + 32) p1 = -1.f;
        }
        float wsum = 0.f;
#pragma unroll
        for (int k = 0; k < TOPK; k++) wsum += selw[k];

        if (lane == 0) {
            const int tok = t0 + t;
#pragma unroll
            for (int k = 0; k < TOPK; k++) {
                const int e = sele[k];
                const int pos = atomicAdd(&g_counts[e], 1);
                if (pos < CAP) {
                    g_slot_token[e * CAP + pos]  = tok;
                    g_slot_weight[e * CAP + pos] = selw[k] / wsum;
                    g_tok_slot[tok * TOPK + k]   = e * CAP + pos;
                } else {
                    g_tok_slot[tok * TOPK + k]   = -1;
                }
            }
        }
    }
}

__global__ __launch_bounds__(256) void prep_kernel(
    const float* __restrict__ x, const float* __restrict__ gate_w,
    const float* __restrict__ Wg, const float* __restrict__ Wu,
    const float* __restrict__ Wd)
{
    const int bid = blockIdx.x;
    if (bid < NB_R) {
        router_body(bid, x, gate_w);
    } else if (bid < NB_R + NB_GU) {
        convert_gu_body(bid - NB_R, Wg, Wu);
    } else {
        convert_d_body(bid - NB_R - NB_GU, Wd);
    }
}

// ---------------- kernel: grouped GEMM1 (fp16 mma + cp.async, SwiGLU) --------
// CTA 128(M) x 64(H), 128 thr (4 warps 2Mx2N), warp 64x32 dual.
// 3-stage pipe (48KB smem -> 3 CTAs/SM), 32 k (2 chunks) per stage.
// Stage (16KB): A [0,8KB) = 2 x 4KB swizzled chunk blocks; G [8KB,12KB);
// U [12KB,16KB).
__global__ __launch_bounds__(128, 3) void gemm1_kernel()
{
    const int e = blockIdx.z;
    const int n_e = min(g_counts[e], CAP);
    const int row0 = blockIdx.x * 128;
    if (row0 >= n_e) return;
    const int by = blockIdx.y;  // 0..5 (col0 = by*64)

    extern __shared__ uint32_t su[];  // 12288 u32 = 48KB
    __shared__ int stok[128];

    const int tid = threadIdx.x, lane = tid & 31, wid = tid >> 5;
    const int wm = wid >> 1, wn = wid & 1;
    const uint32_t sb = smem_u32(su);

    {
        const int r = row0 + tid;
        stok[tid] = (r < n_e) ? g_slot_token[e * CAP + r] : 0;
    }
    __syncthreads();

    const char* srcA = (const char*)g_xh + (size_t)stok[tid] * (D_DIM * 2);
    const uint32_t swA = ((tid >> 2) & 1) ? 16u : 0u;
    const uint32_t dA0 = sb + tid * 32 + swA;
    const uint32_t dA1 = sb + tid * 32 + (16u ^ swA);
    const char* srcG = (const char*)g_wgf +
        ((size_t)e * 96 * 48 + (size_t)by * 8) * 256 + tid * 16;
    const char* srcU = (const char*)g_wuf +
        ((size_t)e * 96 * 48 + (size_t)by * 8) * 256 + tid * 16;

    // stage s -> buffer buf (0..2)
    auto stage = [&](int s, int buf) {
        const uint32_t so = (uint32_t)buf * 16384;
#pragma unroll
        for (int k2 = 0; k2 < 2; k2++) {
            const int c = 2 * s + k2;
            const uint32_t cb = so + (uint32_t)k2 * 4096;
            cp16(dA0 + cb, srcA + (size_t)c * 32);
            cp16(dA1 + cb, srcA + (size_t)c * 32 + 16);
            cp16(sb + so + 8192  + k2 * 2048 + tid * 16, srcG + (size_t)c * 12288);
            cp16(sb + so + 12288 + k2 * 2048 + tid * 16, srcU + (size_t)c * 12288);
        }
    };
    stage(0, 0); cp_commit();
    stage(1, 1); cp_commit();

    float accg[4][4][4] = {}, accu[4][4][4] = {};

    const int NST = 48;  // 96 chunks / 2
    int cur = 0, nxt = 2;  // buffer of stage s; buffer for stage s+2
    for (int s = 0; s < NST; s++) {
        cp_wait<1>();
        __syncthreads();
        if (s + 2 < NST) stage(s + 2, nxt);
        cp_commit();

#pragma unroll
        for (int k2 = 0; k2 < 2; k2++) {
            const uint32_t so_b = (uint32_t)cur * 16384 + (uint32_t)k2 * 4096;
            const uint32_t io = (uint32_t)cur * 4096;
            uint32_t a[4][4];
#pragma unroll
            for (int mf = 0; mf < 4; mf++) {
                const int rl = (wm * 4 + mf) * 16 + (lane & 15);
                const uint32_t ad = sb + so_b + rl * 32 +
                    ((((lane >> 4) ^ ((rl >> 2) & 1))) << 4);
                ldmx4(a[mf][0], a[mf][1], a[mf][2], a[mf][3], ad);
            }
            uint2 fg[4], fu[4];
#pragma unroll
            for (int nf = 0; nf < 4; nf++) {
                const uint32_t o = io + 2048 + k2 * 512 + ((wn * 4 + nf) * 32 + lane) * 2;
                fg[nf] = *(const uint2*)&su[o];
                fu[nf] = *(const uint2*)&su[o + 1024];
            }
#pragma unroll
            for (int mf = 0; mf < 4; mf++)
#pragma unroll
                for (int nf = 0; nf < 4; nf++) {
                    mma16816(accg[mf][nf], a[mf][0], a[mf][1], a[mf][2], a[mf][3],
                             fg[nf].x, fg[nf].y);
                    mma16816(accu[mf][nf], a[mf][0], a[mf][1], a[mf][2], a[mf][3],
                             fu[nf].x, fu[nf].y);
                }
        }
        cur = (cur == 2) ? 0 : cur + 1;
        nxt = (nxt == 2) ? 0 : nxt + 1;
    }

    // epilogue: SwiGLU -> g_actf in gemm2 A-fragment-major layout
    uint4* actf4 = (uint4*)g_actf;
#pragma unroll
    for (int mf = 0; mf < 4; mf++) {
        const int mt = (row0 >> 4) + wm * 4 + mf;
#pragma unroll
        for (int j = 0; j < 2; j++) {
            const int kc2 = by * 4 + wn * 2 + j;
            const float v0 = silu(accg[mf][2 * j][0]) * accu[mf][2 * j][0];
            const float v1 = silu(accg[mf][2 * j][1]) * accu[mf][2 * j][1];
            const float v2 = silu(accg[mf][2 * j][2]) * accu[mf][2 * j][2];
            const float v3 = silu(accg[mf][2 * j][3]) * accu[mf][2 * j][3];
            const float w0 = silu(accg[mf][2 * j + 1][0]) * accu[mf][2 * j + 1][0];
            const float w1 = silu(accg[mf][2 * j + 1][1]) * accu[mf][2 * j + 1][1];
            const float w2 = silu(accg[mf][2 * j + 1][2]) * accu[mf][2 * j + 1][2];
            const float w3 = silu(accg[mf][2 * j + 1][3]) * accu[mf][2 * j + 1][3];
            actf4[((size_t)(e * 64 + mt) * 24 + kc2) * 32 + lane] =
                make_uint4(pack_h2(v0, v1), pack_h2(v2, v3),
                           pack_h2(w0, w1), pack_h2(w2, w3));
        }
    }
}

// ---------------- kernel: grouped GEMM2 (fp16 mma + cp.async, fp16 y) -------
// CTA 128(M) x 128(D), 128 thr (4 warps 2Mx2N), warp 64x64.
// 4-stage pipe, 32 k (2 chunks) per stage; 3 CTAs/SM.
__global__ __launch_bounds__(128, 3) void gemm2_kernel()
{
    const int e = blockIdx.z;
    const int n_e = min(g_counts[e], CAP);
    const int row0 = blockIdx.x * 128;
    if (row0 >= n_e) return;
    const int by = blockIdx.y;  // 0..11 (col0 = by*128)
    const int col0 = by * 128;

    extern __shared__ uint32_t su[];
    __shared__ float sw[128];

    const int tid = threadIdx.x, lane = tid & 31, wid = tid >> 5;
    const int wm = wid >> 1, wn = wid & 1;
    const uint32_t sb = smem_u32(su);

    {
        const int r = row0 + tid;
        sw[tid] = (r < n_e) ? g_slot_weight[e * CAP + r] : 0.f;
    }
    __syncthreads();

    const char* actb = (const char*)g_actf;
    const char* sA0 = actb +
        ((size_t)(e * 64 + (row0 >> 4) + (tid >> 5)) * 24) * 512 + (tid & 31) * 16;
    const char* sA1 = actb +
        ((size_t)(e * 64 + (row0 >> 4) + (tid >> 5) + 4) * 24) * 512 + (tid & 31) * 16;
    const char* sB = (const char*)g_wdf +
        ((size_t)e * 24 * 192 + (size_t)(by * 16)) * 256 + tid * 16;

    auto stage = [&](int s) {
        const uint32_t so = (uint32_t)(s & 3) * 16384;
#pragma unroll
        for (int k2 = 0; k2 < 2; k2++) {
            const int c = 2 * s + k2;
            const uint32_t cb = so + (uint32_t)k2 * 4096;
            cp16(sb + cb + tid * 16,        sA0 + (size_t)c * 512);
            cp16(sb + cb + 2048 + tid * 16, sA1 + (size_t)c * 512);
            cp16(sb + cb + 8192 + tid * 16,        sB + (size_t)c * 49152);
            cp16(sb + cb + 8192 + 2048 + tid * 16, sB + (size_t)c * 49152 + 2048);
        }
    };
    stage(0); cp_commit();
    stage(1); cp_commit();
    stage(2); cp_commit();

    float acc[4][8][4] = {};

    const int NST = 12;  // 24 chunks / 2
    for (int s = 0; s < NST; s++) {
        cp_wait<2>();
        __syncthreads();
        if (s + 3 < NST) stage(s + 3);
        cp_commit();

#pragma unroll
        for (int k2 = 0; k2 < 2; k2++) {
            const uint32_t io = (uint32_t)(s & 3) * 4096 + (uint32_t)k2 * 1024;
            uint4 a[4];
#pragma unroll
            for (int mf = 0; mf < 4; mf++)
                a[mf] = *(const uint4*)&su[io + ((wm * 4 + mf) * 32 + lane) * 4];
            uint2 fb[8];
#pragma unroll
            for (int nf = 0; nf < 8; nf++)
                fb[nf] = *(const uint2*)&su[io + 2048 + ((wn * 8 + nf) * 32 + lane) * 2];
#pragma unroll
            for (int mf = 0; mf < 4; mf++)
#pragma unroll
                for (int nf = 0; nf < 8; nf++)
                    mma16816(acc[mf][nf], a[mf].x, a[mf].y, a[mf].z, a[mf].w,
                             fb[nf].x, fb[nf].y);
        }
    }

    // epilogue: weight-scale rows -> g_yh (fp16 pairs)
    const int g = lane >> 2, t = lane & 3;
    uint32_t* yh = (uint32_t*)g_yh;
#pragma unroll
    for (int mf = 0; mf < 4; mf++) {
        const int ml = wm * 64 + mf * 16 + g;
        const int r = row0 + ml;
        const float w1 = sw[ml], w2 = sw[ml + 8];
#pragma unroll
        for (int nf = 0; nf < 8; nf++) {
            const int col = col0 + wn * 64 + nf * 8 + 2 * t;
            if (r < n_e)
                yh[((size_t)(e * CAP + r) * D_DIM + col) >> 1] =
                    pack_h2(w1 * acc[mf][nf][0], w1 * acc[mf][nf][1]);
            if (r + 8 < n_e)
                yh[((size_t)(e * CAP + r + 8) * D_DIM + col) >> 1] =
                    pack_h2(w2 * acc[mf][nf][2], w2 * acc[mf][nf][3]);
        }
    }
}

// ---------------- kernel: combine (gather-sum per token, fp16 y) ------------
__global__ __launch_bounds__(192) void combine_kernel(float* __restrict__ out)
{
    const int tk = blockIdx.x;
    const int tid = threadIdx.x;
    __shared__ int slots[TOPK];
    if (tid < TOPK) slots[tid] = g_tok_slot[tk * TOPK + tid];
    __syncthreads();

    float a[8] = {};
#pragma unroll
    for (int k = 0; k < TOPK; k++) {
        const int s = slots[k];
        if (s < 0) continue;
        const uint4* row = (const uint4*)(g_yh + (size_t)s * D_DIM);
        uint4 v = row[tid];
        float2 f0 = __half22float2(*(__half2*)&v.x);
        float2 f1 = __half22float2(*(__half2*)&v.y);
        float2 f2 = __half22float2(*(__half2*)&v.z);
        float2 f3 = __half22float2(*(__half2*)&v.w);
        a[0] += f0.x; a[1] += f0.y; a[2] += f1.x; a[3] += f1.y;
        a[4] += f2.x; a[5] += f2.y; a[6] += f3.x; a[7] += f3.y;
    }
    float4* o = (float4*)(out + (size_t)tk * D_DIM + tid * 8);
    o[0] = make_float4(a[0], a[1], a[2], a[3]);
    o[1] = make_float4(a[4], a[5], a[6], a[7]);
}

// ---------------- launcher --------------------------------------------------
extern "C" void kernel_launch(void* const* d_in, const int* in_sizes, int n_in,
                              void* d_out, int out_size)
{
    const float* x      = (const float*)d_in[0];
    const float* gate_w = (const float*)d_in[1];
    const float* W_gate = (const float*)d_in[2];
    const float* W_up   = (const float*)d_in[3];
    const float* W_down = (const float*)d_in[4];
    float* out = (float*)d_out;

    const int prep_smem = 8 * D_DIM * 4 + 8 * E_NUM * 4;  // 51200
    const int gemm1_smem = 49152;
    const int gemm2_smem = 65536;
    cudaFuncSetAttribute(prep_kernel,
                         cudaFuncAttributeMaxDynamicSharedMemorySize, prep_smem);
    cudaFuncSetAttribute(gemm1_kernel,
                         cudaFuncAttributeMaxDynamicSharedMemorySize, gemm1_smem);
    cudaFuncSetAttribute(gemm2_kernel,
                         cudaFuncAttributeMaxDynamicSharedMemorySize, gemm2_smem);

    init_kernel<<<1, 64>>>();
    prep_kernel<<<NB_R + NB_GU + NB_D, 256, prep_smem>>>(
        x, gate_w, W_gate, W_up, W_down);
    gemm1_kernel<<<dim3(CAP / 128, H_DIM / 64, E_NUM), 128, gemm1_smem>>>();
    gemm2_kernel<<<dim3(CAP / 128, D_DIM / 128, E_NUM), 128, gemm2_smem>>>();
    combine_kernel<<<T_NUM, 192>>>(out);
}

// round 15
// speedup vs baseline: 1.0283x; 1.0283x over previous
#include <cuda_runtime.h>
#include <cuda_fp16.h>
#include <math.h>
#include <stdint.h>

#define D_DIM 1536
#define E_NUM 64
#define H_DIM 384
#define TOPK  8
#define CAP   1024
#define T_NUM 4096

// ---------------- scratch (static device globals; no allocations) ----------
__device__ __align__(16) int      g_counts[E_NUM];
__device__ __align__(16) int      g_done[E_NUM];
__device__ __align__(16) int      g_slot_token[E_NUM * CAP];
__device__ __align__(16) float    g_slot_weight[E_NUM * CAP];
__device__ __align__(16) int      g_tok_slot[T_NUM * TOPK];
__device__ __align__(16) __half   g_xh[(size_t)T_NUM * D_DIM];                // 12.6 MB
__device__ __align__(16) uint32_t g_wgf[(size_t)E_NUM * 96 * 48 * 32 * 2];    // 75 MB
__device__ __align__(16) uint32_t g_wuf[(size_t)E_NUM * 96 * 48 * 32 * 2];    // 75 MB
__device__ __align__(16) uint32_t g_wdf[(size_t)E_NUM * 24 * 192 * 32 * 2];   // 75 MB
__device__ __align__(16) uint32_t g_actf[(size_t)E_NUM * 64 * 24 * 128];      // 50 MB
__device__ __align__(16) __half   g_yh[(size_t)E_NUM * CAP * D_DIM];          // 201 MB

// ---------------- helpers ----------------------------------------------------
__device__ __forceinline__ uint32_t pack_h2(float lo, float hi) {
    __half2 h = __floats2half2_rn(lo, hi);
    return *(uint32_t*)&h;
}
__device__ __forceinline__ uint32_t smem_u32(const void* p) {
    return (uint32_t)__cvta_generic_to_shared(p);
}
__device__ __forceinline__ void cp16(uint32_t dst, const void* src) {
    asm volatile("cp.async.cg.shared.global [%0], [%1], 16;"
                 :: "r"(dst), "l"(src) : "memory");
}
__device__ __forceinline__ void cp_commit() {
    asm volatile("cp.async.commit_group;" ::: "memory");
}
template <int N>
__device__ __forceinline__ void cp_wait() {
    asm volatile("cp.async.wait_group %0;" :: "n"(N) : "memory");
}
__device__ __forceinline__ void ldmx4(uint32_t& a0, uint32_t& a1,
                                      uint32_t& a2, uint32_t& a3, uint32_t addr) {
    asm volatile("ldmatrix.sync.aligned.m8n8.x4.shared.b16 {%0,%1,%2,%3}, [%4];"
                 : "=r"(a0), "=r"(a1), "=r"(a2), "=r"(a3) : "r"(addr));
}
__device__ __forceinline__ void mma16816(float c[4],
                                         uint32_t a0, uint32_t a1, uint32_t a2, uint32_t a3,
                                         uint32_t b0, uint32_t b1) {
    asm volatile(
        "mma.sync.aligned.m16n8k16.row.col.f32.f16.f16.f32 "
        "{%0,%1,%2,%3}, {%4,%5,%6,%7}, {%8,%9}, {%0,%1,%2,%3};"
        : "+f"(c[0]), "+f"(c[1]), "+f"(c[2]), "+f"(c[3])
        : "r"(a0), "r"(a1), "r"(a2), "r"(a3), "r"(b0), "r"(b1));
}
__device__ __forceinline__ float silu(float g) { return g / (1.f + expf(-g)); }

// ---------------- kernel 0: init counters -----------------------------------
__global__ void init_kernel() {
    if (threadIdx.x < E_NUM) {
        g_counts[threadIdx.x] = 0;
        g_done[threadIdx.x] = 0;
    }
}

// =============================================================================
// fused prep kernel: router FIRST (overlaps with converters), then converters.
// =============================================================================
#define NB_R  512
#define NB_GU 6144
#define NB_D  1536

extern __shared__ float s_dyn[];

__device__ __forceinline__ void convert_gu_body(
    int bid, const float* __restrict__ Wg, const float* __restrict__ Wu)
{
    const int kc = bid % 96, e = bid / 96;
    const int tid = threadIdx.x, lane = tid & 31, g = lane >> 2, t = lane & 3;
    const size_t wbase = (size_t)e * D_DIM * H_DIM + (size_t)(16 * kc + 2 * t) * H_DIM;
    const float* wg0 = Wg + wbase;
    const float* wu0 = Wu + wbase;
    uint2* og = (uint2*)g_wgf;
    uint2* ou = (uint2*)g_wuf;
#pragma unroll
    for (int p = 0; p < 6; p++) {
        const int nt = (tid >> 5) + 8 * p;
        const int n = 8 * nt + g;
        const size_t oi = ((size_t)(e * 96 + kc) * 48 + nt) * 32 + lane;
        og[oi] = make_uint2(pack_h2(wg0[n], wg0[H_DIM + n]),
                            pack_h2(wg0[8 * H_DIM + n], wg0[9 * H_DIM + n]));
        ou[oi] = make_uint2(pack_h2(wu0[n], wu0[H_DIM + n]),
                            pack_h2(wu0[8 * H_DIM + n], wu0[9 * H_DIM + n]));
    }
}

__device__ __forceinline__ void convert_d_body(
    int bid, const float* __restrict__ Wd)
{
    const int kc = bid % 24, e = bid / 24;
    const int tid = threadIdx.x, lane = tid & 31, g = lane >> 2, t = lane & 3;
    const float* wd0 = Wd + (size_t)e * H_DIM * D_DIM + (size_t)(16 * kc + 2 * t) * D_DIM;
    uint2* od = (uint2*)g_wdf;
#pragma unroll
    for (int p = 0; p < 24; p++) {
        const int nt = (tid >> 5) + 8 * p;
        const int n = 8 * nt + g;
        od[((size_t)(e * 24 + kc) * 192 + nt) * 32 + lane] =
            make_uint2(pack_h2(wd0[n], wd0[D_DIM + n]),
                       pack_h2(wd0[8 * D_DIM + n], wd0[9 * D_DIM + n]));
    }
}

__device__ __forceinline__ void router_body(
    int rbid, const float* __restrict__ x, const float* __restrict__ gate_w)
{
    float (*xs)[D_DIM] = (float (*)[D_DIM])s_dyn;
    float (*lg)[E_NUM] = (float (*)[E_NUM])(s_dyn + 8 * D_DIM);

    const int tid = threadIdx.x;
    const int t0 = rbid * 8;

    const float4* xg = (const float4*)(x + (size_t)t0 * D_DIM);
    float4* xs4 = (float4*)xs;
    for (int i = tid; i < 8 * D_DIM / 4; i += 256) xs4[i] = xg[i];
    __syncthreads();

    {
        uint2* xh2 = (uint2*)(g_xh + (size_t)t0 * D_DIM);
        const float4* xsc = (const float4*)xs;
        for (int i = tid; i < 8 * D_DIM / 4; i += 256) {
            float4 v = xsc[i];
            xh2[i] = make_uint2(pack_h2(v.x, v.y), pack_h2(v.z, v.w));
        }
    }

    const int warp = tid >> 5, lane = tid & 31;

    {
        const int e0 = warp * 8;
        float acc[8][8];
#pragma unroll
        for (int j = 0; j < 8; j++)
#pragma unroll
            for (int t = 0; t < 8; t++) acc[j][t] = 0.f;

        for (int d4 = lane; d4 < D_DIM / 4; d4 += 32) {
            float4 xv[8];
#pragma unroll
            for (int t = 0; t < 8; t++)
                xv[t] = *(const float4*)(&xs[t][d4 * 4]);
            float4 gv[8];
#pragma unroll
            for (int j = 0; j < 8; j++)
                gv[j] = *(const float4*)(gate_w + (size_t)(e0 + j) * D_DIM + d4 * 4);
#pragma unroll
            for (int j = 0; j < 8; j++)
#pragma unroll
                for (int t = 0; t < 8; t++)
                    acc[j][t] = fmaf(gv[j].x, xv[t].x, fmaf(gv[j].y, xv[t].y,
                                 fmaf(gv[j].z, xv[t].z, fmaf(gv[j].w, xv[t].w,
                                 acc[j][t]))));
        }
#pragma unroll
        for (int off = 16; off > 0; off >>= 1)
#pragma unroll
            for (int j = 0; j < 8; j++)
#pragma unroll
                for (int t = 0; t < 8; t++)
                    acc[j][t] += __shfl_xor_sync(0xffffffffu, acc[j][t], off);
        if (lane == 0)
#pragma unroll
            for (int j = 0; j < 8; j++)
#pragma unroll
                for (int t = 0; t < 8; t++) lg[t][e0 + j] = acc[j][t];
    }
    __syncthreads();

    {
        const int t = warp;
        float v0 = lg[t][lane];
        float v1 = lg[t][lane + 32];
        float m = fmaxf(v0, v1);
#pragma unroll
        for (int off = 16; off > 0; off >>= 1)
            m = fmaxf(m, __shfl_xor_sync(0xffffffffu, m, off));
        float e0 = expf(v0 - m), e1 = expf(v1 - m);
        float s = e0 + e1;
#pragma unroll
        for (int off = 16; off > 0; off >>= 1)
            s += __shfl_xor_sync(0xffffffffu, s, off);
        float p0 = e0 / s, p1 = e1 / s;

        float selw[TOPK];
        int   sele[TOPK];
#pragma unroll
        for (int k = 0; k < TOPK; k++) {
            float bv; int bi;
            if (p0 >= p1) { bv = p0; bi = lane; }
            else          { bv = p1; bi = lane + 32; }
#pragma unroll
            for (int off = 16; off > 0; off >>= 1) {
                float ov = __shfl_xor_sync(0xffffffffu, bv, off);
                int   oi = __shfl_xor_sync(0xffffffffu, bi, off);
                if (ov > bv || (ov == bv && oi < bi)) { bv = ov; bi = oi; }
            }
            selw[k] = bv; sele[k] = bi;
            if (bi == lane)      p0 = -1.f;
            if (bi == lane + 32) p1 = -1.f;
        }
        float wsum = 0.f;
#pragma unroll
        for (int k = 0; k < TOPK; k++) wsum += selw[k];

        if (lane == 0) {
            const int tok = t0 + t;
#pragma unroll
            for (int k = 0; k < TOPK; k++) {
                const int e = sele[k];
                const int pos = atomicAdd(&g_counts[e], 1);
                if (pos < CAP) {
                    g_slot_token[e * CAP + pos]  = tok;
                    g_slot_weight[e * CAP + pos] = selw[k] / wsum;
                    g_tok_slot[tok * TOPK + k]   = e * CAP + pos;
                } else {
                    g_tok_slot[tok * TOPK + k]   = -1;
                }
            }
        }
    }
}

__global__ __launch_bounds__(256) void prep_kernel(
    const float* __restrict__ x, const float* __restrict__ gate_w,
    const float* __restrict__ Wg, const float* __restrict__ Wu,
    const float* __restrict__ Wd)
{
    const int bid = blockIdx.x;
    if (bid < NB_R) {
        router_body(bid, x, gate_w);
    } else if (bid < NB_R + NB_GU) {
        convert_gu_body(bid - NB_R, Wg, Wu);
    } else {
        convert_d_body(bid - NB_R - NB_GU, Wd);
    }
}

// =============================================================================
// fused GEMM kernel: blocks [0,3072) = gemm1 (producers, expert-ascending),
// blocks [3072,9216) = gemm2 (consumers, spin on g_done[e]==48).
// Both parts: 128 thr, 64KB smem, 4-stage cp.async pipe.
// =============================================================================
#define NB_G1 3072   // 8 mtiles x 6 by x 64 experts
#define G1_PER_E 48

__device__ __forceinline__ void gemm1_body(int bid)
{
    const int e = bid / 48;
    const int sub = bid % 48;
    const int by = sub / 8;          // 0..5
    const int row0 = (sub % 8) * 128;

    const int n_e = min(g_counts[e], CAP);
    const int tid = threadIdx.x;
    if (row0 >= n_e) {
        if (tid == 0) atomicAdd(&g_done[e], 1);
        return;
    }

    uint32_t* su = (uint32_t*)s_dyn;
    __shared__ int stok[128];

    const int lane = tid & 31, wid = tid >> 5;
    const int wm = wid >> 1, wn = wid & 1;
    const uint32_t sb = smem_u32(su);

    {
        const int r = row0 + tid;
        stok[tid] = (r < n_e) ? g_slot_token[e * CAP + r] : 0;
    }
    __syncthreads();

    const char* srcA = (const char*)g_xh + (size_t)stok[tid] * (D_DIM * 2);
    const uint32_t swA = ((tid >> 2) & 1) ? 16u : 0u;
    const uint32_t dA0 = sb + tid * 32 + swA;
    const uint32_t dA1 = sb + tid * 32 + (16u ^ swA);
    const char* srcG = (const char*)g_wgf +
        ((size_t)e * 96 * 48 + (size_t)by * 8) * 256 + tid * 16;
    const char* srcU = (const char*)g_wuf +
        ((size_t)e * 96 * 48 + (size_t)by * 8) * 256 + tid * 16;

    auto stage = [&](int s) {
        const uint32_t so = (uint32_t)(s & 3) * 16384;
#pragma unroll
        for (int k2 = 0; k2 < 2; k2++) {
            const int c = 2 * s + k2;
            const uint32_t cb = so + (uint32_t)k2 * 4096;
            cp16(dA0 + cb, srcA + (size_t)c * 32);
            cp16(dA1 + cb, srcA + (size_t)c * 32 + 16);
            cp16(sb + so + 8192  + k2 * 2048 + tid * 16, srcG + (size_t)c * 12288);
            cp16(sb + so + 12288 + k2 * 2048 + tid * 16, srcU + (size_t)c * 12288);
        }
    };
    stage(0); cp_commit();
    stage(1); cp_commit();
    stage(2); cp_commit();

    float accg[4][4][4] = {}, accu[4][4][4] = {};

    const int NST = 48;
    for (int s = 0; s < NST; s++) {
        cp_wait<2>();
        __syncthreads();
        if (s + 3 < NST) stage(s + 3);
        cp_commit();

#pragma unroll
        for (int k2 = 0; k2 < 2; k2++) {
            const uint32_t so_b = (uint32_t)(s & 3) * 16384 + (uint32_t)k2 * 4096;
            const uint32_t io = (uint32_t)(s & 3) * 4096;
            uint32_t a[4][4];
#pragma unroll
            for (int mf = 0; mf < 4; mf++) {
                const int rl = (wm * 4 + mf) * 16 + (lane & 15);
                const uint32_t ad = sb + so_b + rl * 32 +
                    ((((lane >> 4) ^ ((rl >> 2) & 1))) << 4);
                ldmx4(a[mf][0], a[mf][1], a[mf][2], a[mf][3], ad);
            }
            uint2 fg[4], fu[4];
#pragma unroll
            for (int nf = 0; nf < 4; nf++) {
                const uint32_t o = io + 2048 + k2 * 512 + ((wn * 4 + nf) * 32 + lane) * 2;
                fg[nf] = *(const uint2*)&su[o];
                fu[nf] = *(const uint2*)&su[o + 1024];
            }
#pragma unroll
            for (int mf = 0; mf < 4; mf++)
#pragma unroll
                for (int nf = 0; nf < 4; nf++) {
                    mma16816(accg[mf][nf], a[mf][0], a[mf][1], a[mf][2], a[mf][3],
                             fg[nf].x, fg[nf].y);
                    mma16816(accu[mf][nf], a[mf][0], a[mf][1], a[mf][2], a[mf][3],
                             fu[nf].x, fu[nf].y);
                }
        }
    }

    // epilogue: SwiGLU -> g_actf (gemm2 A-fragment-major layout)
    uint4* actf4 = (uint4*)g_actf;
#pragma unroll
    for (int mf = 0; mf < 4; mf++) {
        const int mt = (row0 >> 4) + wm * 4 + mf;
#pragma unroll
        for (int j = 0; j < 2; j++) {
            const int kc2 = by * 4 + wn * 2 + j;
            const float v0 = silu(accg[mf][2 * j][0]) * accu[mf][2 * j][0];
            const float v1 = silu(accg[mf][2 * j][1]) * accu[mf][2 * j][1];
            const float v2 = silu(accg[mf][2 * j][2]) * accu[mf][2 * j][2];
            const float v3 = silu(accg[mf][2 * j][3]) * accu[mf][2 * j][3];
            const float w0 = silu(accg[mf][2 * j + 1][0]) * accu[mf][2 * j + 1][0];
            const float w1 = silu(accg[mf][2 * j + 1][1]) * accu[mf][2 * j + 1][1];
            const float w2 = silu(accg[mf][2 * j + 1][2]) * accu[mf][2 * j + 1][2];
            const float w3 = silu(accg[mf][2 * j + 1][3]) * accu[mf][2 * j + 1][3];
            actf4[((size_t)(e * 64 + mt) * 24 + kc2) * 32 + lane] =
                make_uint4(pack_h2(v0, v1), pack_h2(v2, v3),
                           pack_h2(w0, w1), pack_h2(w2, w3));
        }
    }

    // signal completion
    __syncthreads();
    __threadfence();
    if (tid == 0) atomicAdd(&g_done[e], 1);
}

__device__ __forceinline__ void gemm2_body(int bid)
{
    const int e = bid / 96;
    const int sub = bid % 96;
    const int by = sub / 8;          // 0..11
    const int row0 = (sub % 8) * 128;
    const int col0 = by * 128;

    const int tid = threadIdx.x;

    // wait for all 48 gemm1 producers of this expert
    if (tid == 0) {
        while (atomicAdd(&g_done[e], 0) < G1_PER_E)
            __nanosleep(200);
    }
    __syncthreads();
    __threadfence();

    const int n_e = min(g_counts[e], CAP);
    if (row0 >= n_e) return;

    uint32_t* su = (uint32_t*)s_dyn;
    __shared__ float sw[128];

    const int lane = tid & 31, wid = tid >> 5;
    const int wm = wid >> 1, wn = wid & 1;
    const uint32_t sb = smem_u32(su);

    {
        const int r = row0 + tid;
        sw[tid] = (r < n_e) ? g_slot_weight[e * CAP + r] : 0.f;
    }
    __syncthreads();

    const char* actb = (const char*)g_actf;
    const char* sA0 = actb +
        ((size_t)(e * 64 + (row0 >> 4) + (tid >> 5)) * 24) * 512 + (tid & 31) * 16;
    const char* sA1 = actb +
        ((size_t)(e * 64 + (row0 >> 4) + (tid >> 5) + 4) * 24) * 512 + (tid & 31) * 16;
    const char* sB = (const char*)g_wdf +
        ((size_t)e * 24 * 192 + (size_t)(by * 16)) * 256 + tid * 16;

    auto stage = [&](int s) {
        const uint32_t so = (uint32_t)(s & 3) * 16384;
#pragma unroll
        for (int k2 = 0; k2 < 2; k2++) {
            const int c = 2 * s + k2;
            const uint32_t cb = so + (uint32_t)k2 * 4096;
            cp16(sb + cb + tid * 16,        sA0 + (size_t)c * 512);
            cp16(sb + cb + 2048 + tid * 16, sA1 + (size_t)c * 512);
            cp16(sb + cb + 8192 + tid * 16,        sB + (size_t)c * 49152);
            cp16(sb + cb + 8192 + 2048 + tid * 16, sB + (size_t)c * 49152 + 2048);
        }
    };
    stage(0); cp_commit();
    stage(1); cp_commit();
    stage(2); cp_commit();

    float acc[4][8][4] = {};

    const int NST = 12;
    for (int s = 0; s < NST; s++) {
        cp_wait<2>();
        __syncthreads();
        if (s + 3 < NST) stage(s + 3);
        cp_commit();

#pragma unroll
        for (int k2 = 0; k2 < 2; k2++) {
            const uint32_t io = (uint32_t)(s & 3) * 4096 + (uint32_t)k2 * 1024;
            uint4 a[4];
#pragma unroll
            for (int mf = 0; mf < 4; mf++)
                a[mf] = *(const uint4*)&su[io + ((wm * 4 + mf) * 32 + lane) * 4];
            uint2 fb[8];
#pragma unroll
            for (int nf = 0; nf < 8; nf++)
                fb[nf] = *(const uint2*)&su[io + 2048 + ((wn * 8 + nf) * 32 + lane) * 2];
#pragma unroll
            for (int mf = 0; mf < 4; mf++)
#pragma unroll
                for (int nf = 0; nf < 8; nf++)
                    mma16816(acc[mf][nf], a[mf].x, a[mf].y, a[mf].z, a[mf].w,
                             fb[nf].x, fb[nf].y);
        }
    }

    // epilogue: weight-scale rows -> g_yh (fp16 pairs)
    const int g = lane >> 2, t = lane & 3;
    uint32_t* yh = (uint32_t*)g_yh;
#pragma unroll
    for (int mf = 0; mf < 4; mf++) {
        const int ml = wm * 64 + mf * 16 + g;
        const int r = row0 + ml;
        const float w1 = sw[ml], w2 = sw[ml + 8];
#pragma unroll
        for (int nf = 0; nf < 8; nf++) {
            const int col = col0 + wn * 64 + nf * 8 + 2 * t;
            if (r < n_e)
                yh[((size_t)(e * CAP + r) * D_DIM + col) >> 1] =
                    pack_h2(w1 * acc[mf][nf][0], w1 * acc[mf][nf][1]);
            if (r + 8 < n_e)
                yh[((size_t)(e * CAP + r + 8) * D_DIM + col) >> 1] =
                    pack_h2(w2 * acc[mf][nf][2], w2 * acc[mf][nf][3]);
        }
    }
}

__global__ __launch_bounds__(128, 3) void gemm_fused_kernel()
{
    const int bid = blockIdx.x;
    if (bid < NB_G1) gemm1_body(bid);
    else             gemm2_body(bid - NB_G1);
}

// ---------------- kernel: combine (gather-sum per token, fp16 y) ------------
__global__ __launch_bounds__(192) void combine_kernel(float* __restrict__ out)
{
    const int tk = blockIdx.x;
    const int tid = threadIdx.x;
    __shared__ int slots[TOPK];
    if (tid < TOPK) slots[tid] = g_tok_slot[tk * TOPK + tid];
    __syncthreads();

    float a[8] = {};
#pragma unroll
    for (int k = 0; k < TOPK; k++) {
        const int s = slots[k];
        if (s < 0) continue;
        const uint4* row = (const uint4*)(g_yh + (size_t)s * D_DIM);
        uint4 v = row[tid];
        float2 f0 = __half22float2(*(__half2*)&v.x);
        float2 f1 = __half22float2(*(__half2*)&v.y);
        float2 f2 = __half22float2(*(__half2*)&v.z);
        float2 f3 = __half22float2(*(__half2*)&v.w);
        a[0] += f0.x; a[1] += f0.y; a[2] += f1.x; a[3] += f1.y;
        a[4] += f2.x; a[5] += f2.y; a[6] += f3.x; a[7] += f3.y;
    }
    float4* o = (float4*)(out + (size_t)tk * D_DIM + tid * 8);
    o[0] = make_float4(a[0], a[1], a[2], a[3]);
    o[1] = make_float4(a[4], a[5], a[6], a[7]);
}

// ---------------- launcher --------------------------------------------------
extern "C" void kernel_launch(void* const* d_in, const int* in_sizes, int n_in,
                              void* d_out, int out_size)
{
    const float* x      = (const float*)d_in[0];
    const float* gate_w = (const float*)d_in[1];
    const float* W_gate = (const float*)d_in[2];
    const float* W_up   = (const float*)d_in[3];
    const float* W_down = (const float*)d_in[4];
    float* out = (float*)d_out;

    const int prep_smem = 8 * D_DIM * 4 + 8 * E_NUM * 4;  // 51200
    const int gemm_smem = 65536;
    cudaFuncSetAttribute(prep_kernel,
                         cudaFuncAttributeMaxDynamicSharedMemorySize, prep_smem);
    cudaFuncSetAttribute(gemm_fused_kernel,
                         cudaFuncAttributeMaxDynamicSharedMemorySize, gemm_smem);

    init_kernel<<<1, 64>>>();
    prep_kernel<<<NB_R + NB_GU + NB_D, 256, prep_smem>>>(
        x, gate_w, W_gate, W_up, W_down);
    gemm_fused_kernel<<<NB_G1 + 6144, 128, gemm_smem>>>();
    combine_kernel<<<T_NUM, 192>>>(out);
}